// round 1
// baseline (speedup 1.0000x reference)
#include <cuda_runtime.h>

// Problem constants (shape-fixed problem; G derived at launch)
#define M_DIM 1024
#define E_DIM 64
#define S_DIM 2048
#define GS_TOK 8192
#define GEMM_BLOCKS 128      // GS_TOK / 64 tokens per block
#define FILL_BLOCKS 2048

// Scratch (static device arrays -- no allocation)
__device__ float g_proxy_partial[GEMM_BLOCKS * E_DIM];
__device__ int   g_expert[GS_TOK];
__device__ float g_gate[GS_TOK];
__device__ int   g_pos[GS_TOK];
__device__ float g_group_loss[8];

// ---------------------------------------------------------------------------
// K1: fused zero-fill + gating GEMM + softmax/argmax + proxy sums
// Blocks [0,128): GEMM over 64 tokens x 64 experts. Blocks [128, ...): fill.
// ---------------------------------------------------------------------------
__global__ __launch_bounds__(256)
void k1_gemm_fill(const float* __restrict__ X, const float* __restrict__ W,
                  float* __restrict__ out, long long out_size)
{
    __shared__ float smem[4160];   // union: As[64][33] (2112) + Bs[32][64] (2048) == logits[64][65] (4160)
    __shared__ float proxyS[E_DIM];

    int b = blockIdx.x;
    if (b < GEMM_BLOCKS) {
        float* As = smem;          // [64][33] row-major padded
        float* Bs = smem + 2112;   // [32][64]
        int tid = threadIdx.x;
        int tx = tid & 15, ty = tid >> 4;
        if (tid < E_DIM) proxyS[tid] = 0.f;

        float acc[4][4];
        #pragma unroll
        for (int i = 0; i < 4; i++)
            #pragma unroll
            for (int j = 0; j < 4; j++) acc[i][j] = 0.f;

        int tbase = b * 64;
        const float* Xb = X + (long long)tbase * M_DIM;

        for (int kt = 0; kt < M_DIM; kt += 32) {
            // Load A tile: 64 tokens x 32 k (coalesced float4, padded shared rows)
            #pragma unroll
            for (int j = 0; j < 2; j++) {
                int t  = (tid >> 3) + j * 32;   // 0..63
                int kq = tid & 7;               // float4 index within 32
                float4 v = *(const float4*)(Xb + (long long)t * M_DIM + kt + kq * 4);
                float* dst = As + t * 33 + kq * 4;
                dst[0] = v.x; dst[1] = v.y; dst[2] = v.z; dst[3] = v.w;
            }
            // Load B tile: 32 k x 64 experts (row-major, float4)
            #pragma unroll
            for (int j = 0; j < 2; j++) {
                int idx = tid + j * 256;
                int r = idx >> 4, c4 = idx & 15;
                ((float4*)Bs)[r * 16 + c4] = ((const float4*)(W + (long long)(kt + r) * E_DIM))[c4];
            }
            __syncthreads();
            #pragma unroll
            for (int kk = 0; kk < 32; kk++) {
                float a0 = As[(ty * 4 + 0) * 33 + kk];
                float a1 = As[(ty * 4 + 1) * 33 + kk];
                float a2 = As[(ty * 4 + 2) * 33 + kk];
                float a3 = As[(ty * 4 + 3) * 33 + kk];
                float4 bv = ((float4*)Bs)[kk * 16 + tx];
                acc[0][0] += a0 * bv.x; acc[0][1] += a0 * bv.y; acc[0][2] += a0 * bv.z; acc[0][3] += a0 * bv.w;
                acc[1][0] += a1 * bv.x; acc[1][1] += a1 * bv.y; acc[1][2] += a1 * bv.z; acc[1][3] += a1 * bv.w;
                acc[2][0] += a2 * bv.x; acc[2][1] += a2 * bv.y; acc[2][2] += a2 * bv.z; acc[2][3] += a2 * bv.w;
                acc[3][0] += a3 * bv.x; acc[3][1] += a3 * bv.y; acc[3][2] += a3 * bv.z; acc[3][3] += a3 * bv.w;
            }
            __syncthreads();
        }

        // Stage logits to shared [64][65]
        float* L = smem;
        #pragma unroll
        for (int i = 0; i < 4; i++)
            #pragma unroll
            for (int j = 0; j < 4; j++)
                L[(ty * 4 + i) * 65 + tx * 4 + j] = acc[i][j];
        __syncthreads();

        // Softmax + argmax: warp w handles tokens w*8 .. w*8+7; lane covers experts {lane, lane+32}
        int w = tid >> 5, lane = tid & 31;
        float p0 = 0.f, p1 = 0.f;
        #pragma unroll
        for (int i = 0; i < 8; i++) {
            int row = w * 8 + i;
            float L0 = L[row * 65 + lane];
            float L1 = L[row * 65 + lane + 32];
            float v; int idx;
            if (L0 >= L1) { v = L0; idx = lane; } else { v = L1; idx = lane + 32; }
            #pragma unroll
            for (int off = 16; off; off >>= 1) {
                float ov = __shfl_xor_sync(0xffffffffu, v, off);
                int   oi = __shfl_xor_sync(0xffffffffu, idx, off);
                if (ov > v || (ov == v && oi < idx)) { v = ov; idx = oi; }
            }
            float e0 = expf(L0 - v);
            float e1 = expf(L1 - v);
            float s = e0 + e1;
            #pragma unroll
            for (int off = 16; off; off >>= 1)
                s += __shfl_xor_sync(0xffffffffu, s, off);
            float inv = 1.0f / s;      // gate of argmax = exp(0)/s
            p0 += e0 * inv;
            p1 += e1 * inv;
            if (lane == 0) {
                int t = tbase + row;
                g_expert[t] = idx;
                g_gate[t]   = inv;
            }
        }
        atomicAdd(&proxyS[lane], p0);
        atomicAdd(&proxyS[lane + 32], p1);
        __syncthreads();
        if (tid < E_DIM) g_proxy_partial[b * E_DIM + tid] = proxyS[tid];
    } else {
        // Zero-fill the whole output (combine + dispatch + aux slot region)
        long long n4  = out_size >> 2;
        long long nth = (long long)(gridDim.x - GEMM_BLOCKS) * 256;
        long long fid = (long long)(b - GEMM_BLOCKS) * 256 + threadIdx.x;
        float4 z = make_float4(0.f, 0.f, 0.f, 0.f);
        float4* o4 = (float4*)out;
        for (long long i = fid; i < n4; i += nth) o4[i] = z;
        for (long long i = n4 * 4 + fid; i < out_size; i += nth) out[i] = 0.f;
    }
}

// ---------------------------------------------------------------------------
// K2: per-group position-in-expert scan + capacity drop + aux loss pieces
// grid = G blocks of 1024 threads; group of S=2048 tokens each.
// ---------------------------------------------------------------------------
__global__ __launch_bounds__(1024)
void k2_scan(int C)
{
    __shared__ int hist[64 * E_DIM];       // [chunk][expert]
    __shared__ unsigned char rank8[S_DIM];
    __shared__ unsigned char ex8[S_DIM];
    __shared__ float redS[E_DIM];

    int g = blockIdx.x;
    int tid = threadIdx.x;
    for (int i = tid; i < 64 * E_DIM; i += 1024) hist[i] = 0;
    __syncthreads();

    int lane = tid & 31;
    unsigned lt = (1u << lane) - 1u;

    // Phase 1: per-32-token-chunk histograms + in-chunk ranks via match_any
    #pragma unroll
    for (int h = 0; h < 2; h++) {
        int s = h * 1024 + tid;
        int e = g_expert[g * S_DIM + s];
        unsigned m = __match_any_sync(0xffffffffu, e);
        int r = __popc(m & lt);
        rank8[s] = (unsigned char)r;
        ex8[s]   = (unsigned char)e;
        if (r == 0) hist[(s >> 5) * E_DIM + e] = __popc(m);  // one writer per (chunk,e)
    }
    __syncthreads();

    // Phase 2: exclusive prefix over chunks (thread per expert) + aux-loss term
    if (tid < E_DIM) {
        int e = tid, run = 0;
        for (int c = 0; c < 64; c++) {
            int v = hist[c * E_DIM + e];
            hist[c * E_DIM + e] = run;
            run += v;
        }
        float proxy = 0.f;
        for (int bb = 0; bb < GEMM_BLOCKS / 4; bb++)
            proxy += g_proxy_partial[(g * (GEMM_BLOCKS / 4) + bb) * E_DIM + e];
        const float invden = 1.0f / (2048.0f * 1.000001f);
        redS[tid] = (proxy * invden) * ((float)run * invden);
    }
    __syncthreads();
    if (tid < 32) {
        float v = redS[tid] + redS[tid + 32];
        #pragma unroll
        for (int off = 16; off; off >>= 1)
            v += __shfl_xor_sync(0xffffffffu, v, off);
        if (tid == 0) g_group_loss[g] = v;
    }
    __syncthreads();

    // Phase 3: final positions + capacity mask
    #pragma unroll
    for (int h = 0; h < 2; h++) {
        int s = h * 1024 + tid;
        int e = ex8[s];
        int pos = hist[(s >> 5) * E_DIM + e] + (int)rank8[s];
        int t = g * S_DIM + s;
        g_pos[t] = pos;
        if (pos >= C) g_gate[t] = 0.f;   // dropped token
    }
}

// ---------------------------------------------------------------------------
// K3: scatter nonzeros + aux loss scalar
// ---------------------------------------------------------------------------
__global__ void k3_scatter(float* __restrict__ out, long long half, int C,
                           long long aux_idx, float aux_scale, int G, int GS)
{
    int t = blockIdx.x * 256 + threadIdx.x;
    if (t == 0) {
        float a = 0.f;
        for (int g = 0; g < G; g++) a += g_group_loss[g];
        out[aux_idx] = a * aux_scale;
    }
    if (t < GS) {
        float v = g_gate[t];
        if (v != 0.f) {
            long long idx = ((long long)t * E_DIM + g_expert[t]) * C + g_pos[t];
            out[idx]        = v;
            out[half + idx] = 1.0f;
        }
    }
}

extern "C" void kernel_launch(void* const* d_in, const int* in_sizes, int n_in,
                              void* d_out, int out_size)
{
    const float* X = (const float*)d_in[0];   // inputs [G,S,M] fp32
    const float* W = (const float*)d_in[1];   // gating_weight [M,E] fp32
    float* out = (float*)d_out;

    long long osz  = (long long)out_size;          // 2*G*S*E*C + 1
    long long half = (osz - 1) / 2;                // size of combine tensor
    int GS = in_sizes[0] / M_DIM;                  // 8192
    int C  = (int)(half / ((long long)GS * E_DIM)); // 160
    int G  = GS / S_DIM;                            // 4
    // aux = mean_{G,E}(proxy*density) * E*E*0.01  ->  sum * (E*E*0.01)/(G*E)
    float aux_scale = (float)((double)E_DIM * E_DIM * 0.01 / ((double)G * E_DIM));

    k1_gemm_fill<<<GEMM_BLOCKS + FILL_BLOCKS, 256>>>(X, W, out, osz);
    k2_scan<<<G, 1024>>>(C);
    k3_scatter<<<(GS + 255) / 256, 256>>>(out, half, C, osz - 1, aux_scale, G, GS);
}

// round 2
// speedup vs baseline: 1.0330x; 1.0330x over previous
#include <cuda_runtime.h>

#define M_DIM 1024
#define E_DIM 64
#define S_DIM 2048
#define GS_TOK 8192
#define GEMM_BLOCKS 128      // 64 tokens per block
#define FILL_BLOCKS 2048

__device__ float g_proxy_partial[GEMM_BLOCKS * E_DIM];
__device__ int   g_expert[GS_TOK];
__device__ float g_gate[GS_TOK];
__device__ float g_group_loss[8];
__device__ unsigned int g_loss_cnt;

// ---------------------------------------------------------------------------
// K1: fused zero-fill + gating GEMM (f32x2 packed FFMA) + softmax/argmax
// ---------------------------------------------------------------------------
__global__ __launch_bounds__(256)
void k1_gemm_fill(const float* __restrict__ X, const float* __restrict__ W,
                  float* __restrict__ out, long long out_size)
{
    __shared__ float smem[4160];   // As[64][33] (2112) + Bs[32][64] (2048) == L[64][65]
    __shared__ float proxyS[E_DIM];

    int b = blockIdx.x;
    if (b < GEMM_BLOCKS) {
        if (b == 0 && threadIdx.x == 0) g_loss_cnt = 0;   // reset for this replay

        float* As = smem;
        float* Bs = smem + 2112;
        int tid = threadIdx.x;
        int tx = tid & 15, ty = tid >> 4;
        if (tid < E_DIM) proxyS[tid] = 0.f;

        // 4 rows x 4 experts, experts packed in f32x2 pairs
        unsigned long long acc2[4][2];
        #pragma unroll
        for (int i = 0; i < 4; i++) { acc2[i][0] = 0ull; acc2[i][1] = 0ull; }

        int tbase = b * 64;
        const float* Xb = X + (long long)tbase * M_DIM;

        for (int kt = 0; kt < M_DIM; kt += 32) {
            #pragma unroll
            for (int j = 0; j < 2; j++) {
                int t  = (tid >> 3) + j * 32;
                int kq = tid & 7;
                float4 v = *(const float4*)(Xb + (long long)t * M_DIM + kt + kq * 4);
                float* dst = As + t * 33 + kq * 4;
                dst[0] = v.x; dst[1] = v.y; dst[2] = v.z; dst[3] = v.w;
            }
            #pragma unroll
            for (int j = 0; j < 2; j++) {
                int idx = tid + j * 256;
                int r = idx >> 4, c4 = idx & 15;
                ((float4*)Bs)[r * 16 + c4] = ((const float4*)(W + (long long)(kt + r) * E_DIM))[c4];
            }
            __syncthreads();
            #pragma unroll
            for (int kk = 0; kk < 32; kk++) {
                ulonglong2 bq = *((const ulonglong2*)(Bs + kk * 64) + tx);
                #pragma unroll
                for (int i = 0; i < 4; i++) {
                    float a = As[(ty * 4 + i) * 33 + kk];
                    unsigned long long ap;
                    asm("mov.b64 %0, {%1, %1};" : "=l"(ap) : "f"(a));
                    asm("fma.rn.f32x2 %0, %1, %2, %0;" : "+l"(acc2[i][0]) : "l"(ap), "l"(bq.x));
                    asm("fma.rn.f32x2 %0, %1, %2, %0;" : "+l"(acc2[i][1]) : "l"(ap), "l"(bq.y));
                }
            }
            __syncthreads();
        }

        // Stage logits to shared [64][65]
        float* L = smem;
        #pragma unroll
        for (int i = 0; i < 4; i++) {
            float2 v0 = *reinterpret_cast<float2*>(&acc2[i][0]);
            float2 v1 = *reinterpret_cast<float2*>(&acc2[i][1]);
            float* row = L + (ty * 4 + i) * 65 + tx * 4;
            row[0] = v0.x; row[1] = v0.y; row[2] = v1.x; row[3] = v1.y;
        }
        __syncthreads();

        // Softmax + argmax: warp w handles 8 tokens; lane covers experts {lane, lane+32}
        int w = tid >> 5, lane = tid & 31;
        float p0 = 0.f, p1 = 0.f;
        #pragma unroll
        for (int i = 0; i < 8; i++) {
            int row = w * 8 + i;
            float L0 = L[row * 65 + lane];
            float L1 = L[row * 65 + lane + 32];
            float v; int idx;
            if (L0 >= L1) { v = L0; idx = lane; } else { v = L1; idx = lane + 32; }
            #pragma unroll
            for (int off = 16; off; off >>= 1) {
                float ov = __shfl_xor_sync(0xffffffffu, v, off);
                int   oi = __shfl_xor_sync(0xffffffffu, idx, off);
                if (ov > v || (ov == v && oi < idx)) { v = ov; idx = oi; }
            }
            float e0 = expf(L0 - v);
            float e1 = expf(L1 - v);
            float s = e0 + e1;
            #pragma unroll
            for (int off = 16; off; off >>= 1)
                s += __shfl_xor_sync(0xffffffffu, s, off);
            float inv = 1.0f / s;
            p0 += e0 * inv;
            p1 += e1 * inv;
            if (lane == 0) {
                int t = tbase + row;
                g_expert[t] = idx;
                g_gate[t]   = inv;
            }
        }
        atomicAdd(&proxyS[lane], p0);
        atomicAdd(&proxyS[lane + 32], p1);
        __syncthreads();
        if (tid < E_DIM) g_proxy_partial[b * E_DIM + tid] = proxyS[tid];
    } else {
        // Contiguous-chunk zero fill with streaming stores
        long long n4  = out_size >> 2;
        long long fb  = b - GEMM_BLOCKS;
        long long per = n4 / FILL_BLOCKS;
        long long rem = n4 - per * FILL_BLOCKS;
        long long base = fb * per + (fb < rem ? fb : rem);
        if (fb < rem) per++;

        float4 z = make_float4(0.f, 0.f, 0.f, 0.f);
        float4* dst = (float4*)out + base;
        long long i = threadIdx.x;
        for (; i + 768 < per; i += 1024) {
            __stcs(dst + i,       z);
            __stcs(dst + i + 256, z);
            __stcs(dst + i + 512, z);
            __stcs(dst + i + 768, z);
        }
        for (; i < per; i += 256) __stcs(dst + i, z);

        // scalar tail (incl. aux slot) handled by first fill block
        if (fb == 0) {
            for (long long t = n4 * 4 + threadIdx.x; t < out_size; t += 256)
                out[t] = 0.f;
        }
    }
}

// ---------------------------------------------------------------------------
// K2: position-in-expert scan + capacity drop + direct scatter + aux loss
// grid = G blocks x 1024 threads
// ---------------------------------------------------------------------------
__global__ __launch_bounds__(1024)
void k2_scan_scatter(float* __restrict__ out, long long half, int C,
                     long long aux_idx, float aux_scale, int G)
{
    __shared__ int hist[64 * E_DIM];
    __shared__ unsigned char rank8[S_DIM];
    __shared__ unsigned char ex8[S_DIM];
    __shared__ float redS[E_DIM];

    int g = blockIdx.x;
    int tid = threadIdx.x;
    for (int i = tid; i < 64 * E_DIM; i += 1024) hist[i] = 0;
    __syncthreads();

    int lane = tid & 31;
    unsigned lt = (1u << lane) - 1u;

    // Phase 1: per-32-token-chunk histogram + in-chunk rank
    #pragma unroll
    for (int h = 0; h < 2; h++) {
        int s = h * 1024 + tid;
        int e = g_expert[g * S_DIM + s];
        unsigned m = __match_any_sync(0xffffffffu, e);
        int r = __popc(m & lt);
        rank8[s] = (unsigned char)r;
        ex8[s]   = (unsigned char)e;
        if (r == 0) hist[(s >> 5) * E_DIM + e] = __popc(m);
    }
    __syncthreads();

    // Phase 2: exclusive prefix over chunks + per-group aux term
    if (tid < E_DIM) {
        int e = tid, run = 0;
        for (int c = 0; c < 64; c++) {
            int v = hist[c * E_DIM + e];
            hist[c * E_DIM + e] = run;
            run += v;
        }
        float proxy = 0.f;
        for (int bb = 0; bb < GEMM_BLOCKS / 4; bb++)
            proxy += g_proxy_partial[(g * (GEMM_BLOCKS / 4) + bb) * E_DIM + e];
        const float invden = 1.0f / (2048.0f * 1.000001f);
        redS[tid] = (proxy * invden) * ((float)run * invden);
    }
    __syncthreads();
    if (tid < 32) {
        float v = redS[tid] + redS[tid + 32];
        #pragma unroll
        for (int off = 16; off; off >>= 1)
            v += __shfl_xor_sync(0xffffffffu, v, off);
        if (tid == 0) {
            g_group_loss[g] = v;
            __threadfence();
            atomicAdd(&g_loss_cnt, 1u);
        }
    }

    // Deterministic cross-group aux sum: block 0 thread 0 waits for all groups
    if (g == 0 && tid == 0) {
        while (atomicAdd(&g_loss_cnt, 0u) < (unsigned)G) { }
        float a = 0.f;
        for (int gg = 0; gg < G; gg++) a += g_group_loss[gg];
        out[aux_idx] = a * aux_scale;
    }
    __syncthreads();

    // Phase 3: final positions + capacity mask + scatter
    #pragma unroll
    for (int h = 0; h < 2; h++) {
        int s = h * 1024 + tid;
        int e = ex8[s];
        int pos = hist[(s >> 5) * E_DIM + e] + (int)rank8[s];
        int t = g * S_DIM + s;
        if (pos < C) {
            float v = g_gate[t];
            long long idx = ((long long)t * E_DIM + e) * C + pos;
            out[idx]        = v;
            out[half + idx] = 1.0f;
        }
    }
}

extern "C" void kernel_launch(void* const* d_in, const int* in_sizes, int n_in,
                              void* d_out, int out_size)
{
    const float* X = (const float*)d_in[0];
    const float* W = (const float*)d_in[1];
    float* out = (float*)d_out;

    long long osz  = (long long)out_size;
    long long half = (osz - 1) / 2;
    int GS = in_sizes[0] / M_DIM;                    // 8192
    int C  = (int)(half / ((long long)GS * E_DIM));  // 160
    int G  = GS / S_DIM;                             // 4
    float aux_scale = (float)((double)E_DIM * E_DIM * 0.01 / ((double)G * E_DIM));

    k1_gemm_fill<<<GEMM_BLOCKS + FILL_BLOCKS, 256>>>(X, W, out, osz);
    k2_scan_scatter<<<G, 1024>>>(out, half, C, osz - 1, aux_scale, G);
}